// round 9
// baseline (speedup 1.0000x reference)
#include <cuda_runtime.h>
#include <cuda_fp16.h>
#include <cuda_bf16.h>
#include <cstdint>
#include <math.h>

#define MAXN 100000
#define MAXE 1600000
#define FD   128      // IN == HID == 128
#define OUTC 64

// ---------------- scratch (device globals; no allocation allowed) ----------
// Invariant: g_cnt / g_status / g_ticket are zero before and after every run.
__device__ __nv_bfloat16 g_bufU[MAXN * FD];  // U (gemm1 out), later V
__device__ __nv_bfloat16 g_bufH[MAXN * FD];  // h (agg1 out)
__device__ int    g_cnt[MAXN];
__device__ int    g_rowptr[MAXN + 1];
__device__ int    g_cursor[MAXN];
__device__ __align__(16) int2 g_csrw[MAXE];  // (src index, dinv[src] bits)
__device__ float  g_dinv[MAXN];
__device__ unsigned long long g_status[512];
__device__ unsigned int g_ticket;

// ================= packed f32x2 helpers (sm_100+ base PTX) ==================
__device__ __forceinline__ void ffma2(unsigned long long& acc,
                                      unsigned long long xy, unsigned long long w2) {
    asm("fma.rn.f32x2 %0, %1, %2, %0;" : "+l"(acc) : "l"(xy), "l"(w2));
}
__device__ __forceinline__ void fmul2(unsigned long long& acc, unsigned long long w2) {
    asm("mul.rn.f32x2 %0, %0, %1;" : "+l"(acc) : "l"(w2));
}
// bf16x2 word -> packed f32x2 {lo<<16, hi&mask} (exact)
__device__ __forceinline__ unsigned long long bf2f(uint32_t v) {
    unsigned long long r;
    asm("{\n\t.reg .b32 lo, hi;\n\t"
        "shl.b32 lo, %1, 16;\n\t"
        "and.b32 hi, %1, 0xFFFF0000;\n\t"
        "mov.b64 %0, {lo, hi};\n\t}" : "=l"(r) : "r"(v));
    return r;
}
__device__ __forceinline__ unsigned long long packww(uint32_t wbits) {
    unsigned long long r;
    asm("mov.b64 %0, {%1, %1};" : "=l"(r) : "r"(wbits));
    return r;
}
__device__ __forceinline__ float2 unpack2(unsigned long long v) {
    uint32_t a, b;
    asm("mov.b64 {%0, %1}, %2;" : "=r"(a), "=r"(b) : "l"(v));
    return make_float2(__uint_as_float(a), __uint_as_float(b));
}

// ---------------- single-pass scan (decoupled lookback) ---------------------
__global__ void k_scan_lb(int n) {
    __shared__ int s_vbid;
    __shared__ int s_excl;
    __shared__ int wsum[8], woff[8];
    int tid = threadIdx.x, lane = tid & 31, w = tid >> 5;

    if (tid == 0) s_vbid = (int)atomicAdd(&g_ticket, 1u);
    __syncthreads();
    int vbid = s_vbid;
    int i = vbid * 256 + tid;

    int val = 0;
    if (i < n) { val = g_cnt[i]; g_cnt[i] = 0; }   // consume + self-clean
    int x = val;
#pragma unroll
    for (int o = 1; o < 32; o <<= 1) {
        int t = __shfl_up_sync(0xFFFFFFFFu, x, o);
        if (lane >= o) x += t;
    }
    if (lane == 31) wsum[w] = x;
    __syncthreads();
    if (tid < 8) {
        int ws = wsum[tid];
        int y = ws;
#pragma unroll
        for (int o = 1; o < 8; o <<= 1) {
            int t = __shfl_up_sync(0xFFu, y, o);
            if (tid >= o) y += t;
        }
        woff[tid] = y - ws;
        if (tid == 7) wsum[0] = y;
    }
    __syncthreads();
    int incl = woff[w] + x;
    int agg = wsum[0];

    if (tid == 0) {
        if (vbid == 0) {
            atomicExch(&g_status[0], (2ULL << 32) | (unsigned long long)(unsigned)agg);
            s_excl = 0;
        } else {
            atomicExch(&g_status[vbid], (1ULL << 32) | (unsigned long long)(unsigned)agg);
            int sum = 0;
            int p = vbid - 1;
            while (true) {
                unsigned long long s = atomicAdd(&g_status[p], 0ULL);
                unsigned flag = (unsigned)(s >> 32);
                if (flag == 0u) continue;
                sum += (int)(unsigned)s;
                if (flag == 2u) break;
                p--;
            }
            atomicExch(&g_status[vbid], (2ULL << 32) | (unsigned long long)(unsigned)(sum + agg));
            s_excl = sum;
        }
    }
    __syncthreads();
    int base = s_excl;

    if (i < n) {
        int excl = base + incl - val;
        g_rowptr[i] = excl;
        g_cursor[i] = excl;
        g_dinv[i] = rsqrtf((float)val + 1.0f);
        if (i == n - 1) g_rowptr[n] = base + incl;
    }
}

// ---------------- CSR fill (2 edges/thread) + lookback-state cleanup --------
__global__ void k_fill(const int* __restrict__ ei, int e) {
    int gid = blockIdx.x * blockDim.x + threadIdx.x;
    if (gid < 512) g_status[gid] = 0ULL;
    if (gid == 0) g_ticket = 0u;

    int i2 = gid * 2;
    if (i2 + 1 < e) {
        int2 ss = __ldg((const int2*)&ei[i2]);
        int2 dd = __ldg((const int2*)&ei[e + i2]);
        float w0 = __ldg(&g_dinv[ss.x]);
        float w1 = __ldg(&g_dinv[ss.y]);
        int p0 = atomicAdd(&g_cursor[dd.x], 1);
        g_csrw[p0] = make_int2(ss.x, __float_as_int(w0));
        int p1 = atomicAdd(&g_cursor[dd.y], 1);
        g_csrw[p1] = make_int2(ss.y, __float_as_int(w1));
    } else if (i2 < e) {
        int s = __ldg(&ei[i2]);
        int d = __ldg(&ei[e + i2]);
        float w = __ldg(&g_dinv[s]);
        int p = atomicAdd(&g_cursor[d], 1);
        g_csrw[p] = make_int2(s, __float_as_int(w));
    }
}

// ---------------- bf16 gather core (packed f32x2 math) ----------------------
// one warp per node; lane = 4 bf16 (uint2 = 2 bf16x2 words).
__device__ __forceinline__ float4 agg_gather(const __nv_bfloat16* __restrict__ X,
                                             int node, int lane, float di) {
    const uint2* x2 = (const uint2*)X;   // 32 uint2 per row
    unsigned long long di2 = packww(__float_as_int(di));

    uint2 sr = __ldg(&x2[(size_t)node * 32 + lane]);
    unsigned long long a01 = bf2f(sr.x);
    unsigned long long a23 = bf2f(sr.y);
    fmul2(a01, di2);
    fmul2(a23, di2);

    int s0 = __ldg(&g_rowptr[node]), s1 = __ldg(&g_rowptr[node + 1]);
    int e = s0;

    // peel to even index for int4 pair loads
    if (e < s1 && (e & 1)) {
        int2 p = __ldg(&g_csrw[e]);
        unsigned long long w2 = packww((uint32_t)p.y);
        uint2 r = __ldg(&x2[(size_t)p.x * 32 + lane]);
        ffma2(a01, bf2f(r.x), w2);
        ffma2(a23, bf2f(r.y), w2);
        e++;
    }
    for (; e + 4 <= s1; e += 4) {
        int4 q0 = __ldg((const int4*)&g_csrw[e]);       // edges e, e+1
        int4 q1 = __ldg((const int4*)&g_csrw[e + 2]);   // edges e+2, e+3
        uint2 r0 = __ldg(&x2[(size_t)q0.x * 32 + lane]);
        uint2 r1 = __ldg(&x2[(size_t)q0.z * 32 + lane]);
        uint2 r2 = __ldg(&x2[(size_t)q1.x * 32 + lane]);
        uint2 r3 = __ldg(&x2[(size_t)q1.z * 32 + lane]);
        unsigned long long w0 = packww((uint32_t)q0.y);
        unsigned long long w1 = packww((uint32_t)q0.w);
        unsigned long long w2 = packww((uint32_t)q1.y);
        unsigned long long w3 = packww((uint32_t)q1.w);
        ffma2(a01, bf2f(r0.x), w0); ffma2(a23, bf2f(r0.y), w0);
        ffma2(a01, bf2f(r1.x), w1); ffma2(a23, bf2f(r1.y), w1);
        ffma2(a01, bf2f(r2.x), w2); ffma2(a23, bf2f(r2.y), w2);
        ffma2(a01, bf2f(r3.x), w3); ffma2(a23, bf2f(r3.y), w3);
    }
    if (e + 2 <= s1) {
        int4 q0 = __ldg((const int4*)&g_csrw[e]);
        uint2 r0 = __ldg(&x2[(size_t)q0.x * 32 + lane]);
        uint2 r1 = __ldg(&x2[(size_t)q0.z * 32 + lane]);
        unsigned long long w0 = packww((uint32_t)q0.y);
        unsigned long long w1 = packww((uint32_t)q0.w);
        ffma2(a01, bf2f(r0.x), w0); ffma2(a23, bf2f(r0.y), w0);
        ffma2(a01, bf2f(r1.x), w1); ffma2(a23, bf2f(r1.y), w1);
        e += 2;
    }
    if (e < s1) {
        int2 p = __ldg(&g_csrw[e]);
        unsigned long long w2 = packww((uint32_t)p.y);
        uint2 r = __ldg(&x2[(size_t)p.x * 32 + lane]);
        ffma2(a01, bf2f(r.x), w2);
        ffma2(a23, bf2f(r.y), w2);
    }
    fmul2(a01, di2);
    fmul2(a23, di2);
    float2 f01 = unpack2(a01);
    float2 f23 = unpack2(a23);
    return make_float4(f01.x, f01.y, f23.x, f23.y);
}

// ---- agg1: h = Agg(U) + b1  (bf16 in, bf16 out) ----------------------------
__global__ void k_agg_bias(const __nv_bfloat16* __restrict__ X,
                           __nv_bfloat16* __restrict__ Y,
                           const float* __restrict__ bias, int n) {
    int gw = (blockIdx.x * blockDim.x + threadIdx.x) >> 5;
    int lane = threadIdx.x & 31;
    if (gw >= n) return;
    float di = __ldg(&g_dinv[gw]);
    float4 acc = agg_gather(X, gw, lane, di);
    float4 b = __ldg((const float4*)&bias[lane * 4]);
    __nv_bfloat162 h01 = __float22bfloat162_rn(make_float2(acc.x + b.x, acc.y + b.y));
    __nv_bfloat162 h23 = __float22bfloat162_rn(make_float2(acc.z + b.z, acc.w + b.w));
    uint2 st;
    st.x = *(uint32_t*)&h01;
    st.y = *(uint32_t*)&h23;
    ((uint2*)Y)[(size_t)gw * 32 + lane] = st;
}

// ---- agg2: [mu|ls] = Agg(V)+bias; out = mu + init*exp(ls) ------------------
__global__ void k_agg_out(const __nv_bfloat16* __restrict__ X,
                          const float* __restrict__ bmu, const float* __restrict__ bls,
                          const float* __restrict__ initd,
                          float* __restrict__ out, int n) {
    int gw = (blockIdx.x * blockDim.x + threadIdx.x) >> 5;
    int lane = threadIdx.x & 31;
    if (gw >= n) return;
    float di = __ldg(&g_dinv[gw]);
    float4 v = agg_gather(X, gw, lane, di);
    float4 b = (lane < 16) ? __ldg((const float4*)&bmu[lane * 4])
                           : __ldg((const float4*)&bls[lane * 4 - 64]);
    v.x += b.x; v.y += b.y; v.z += b.z; v.w += b.w;
    float4 p;
    p.x = __shfl_xor_sync(0xFFFFFFFFu, v.x, 16);
    p.y = __shfl_xor_sync(0xFFFFFFFFu, v.y, 16);
    p.z = __shfl_xor_sync(0xFFFFFFFFu, v.z, 16);
    p.w = __shfl_xor_sync(0xFFFFFFFFu, v.w, 16);
    if (lane < 16) {
        float4 ini = __ldg((const float4*)&initd[(size_t)gw * 64 + lane * 4]);
        float4 o;
        o.x = v.x + ini.x * expf(p.x);
        o.y = v.y + ini.y * expf(p.y);
        o.z = v.z + ini.z * expf(p.z);
        o.w = v.w + ini.w * expf(p.w);
        *(float4*)&out[(size_t)gw * 64 + lane * 4] = o;
    }
}

// ================= shared GEMM pieces =======================================
#define KS_B 136
#define SOFF_BH 0
#define SOFF_BL (128 * KS_B * 2)
#define SMEM_MMA (SOFF_BL + 128 * KS_B * 2)

__device__ __forceinline__ void split2(float a, float b, uint32_t& hi, uint32_t& lo) {
    __nv_bfloat16 ah = __float2bfloat16(a), bh = __float2bfloat16(b);
    float ar = a - __bfloat162float(ah);
    float br = b - __bfloat162float(bh);
    __nv_bfloat16 al = __float2bfloat16(ar), bl = __float2bfloat16(br);
    __nv_bfloat162 h; h.x = ah; h.y = bh;
    __nv_bfloat162 l; l.x = al; l.y = bl;
    hi = *(uint32_t*)&h;
    lo = *(uint32_t*)&l;
}

__device__ __forceinline__ uint32_t smem_u32(const void* p) {
    uint32_t a;
    asm("{ .reg .u64 t; cvta.to.shared.u64 t, %1; cvt.u32.u64 %0, t; }" : "=r"(a) : "l"(p));
    return a;
}

__device__ __forceinline__ void mma_bf16(float& c0, float& c1, float& c2, float& c3,
                                         uint32_t a0, uint32_t a1, uint32_t a2, uint32_t a3,
                                         uint32_t b0, uint32_t b1) {
    asm volatile(
        "mma.sync.aligned.m16n8k16.row.col.f32.bf16.bf16.f32 "
        "{%0,%1,%2,%3}, {%4,%5,%6,%7}, {%8,%9}, {%0,%1,%2,%3};"
        : "+f"(c0), "+f"(c1), "+f"(c2), "+f"(c3)
        : "r"(a0), "r"(a1), "r"(a2), "r"(a3), "r"(b0), "r"(b1));
}

__device__ __forceinline__ void ldsm_x2(uint32_t& r0, uint32_t& r1, uint32_t addr) {
    asm volatile("ldmatrix.sync.aligned.m8n8.x2.shared.b16 {%0, %1}, [%2];"
        : "=r"(r0), "=r"(r1) : "r"(addr));
}

__device__ __forceinline__ uint32_t bf16x2_pack(float a, float b) {
    __nv_bfloat162 h = __float22bfloat162_rn(make_float2(a, b));
    return *(uint32_t*)&h;
}

// ---- gemm1: split-bf16 3-pass, fp32 A, fused degree count, bf16 out --------
__global__ void __launch_bounds__(256)
k_mma_gemm(const float* __restrict__ A,
           const float* __restrict__ Wa,
           __nv_bfloat16* __restrict__ C, int n,
           const int* __restrict__ ei, int e) {
    extern __shared__ char smem[];
    uint16_t* BH = (uint16_t*)(smem + SOFF_BH);
    uint16_t* BL = (uint16_t*)(smem + SOFF_BL);
    int tid = threadIdx.x;
    int wid = tid >> 5, lane = tid & 31;
    int row0 = blockIdx.x * 128;

    {
        int stride = gridDim.x * blockDim.x;
        for (int i = blockIdx.x * blockDim.x + tid; i < e; i += stride)
            atomicAdd(&g_cnt[__ldg(&ei[e + i])], 1);
    }

    {
        int col = tid >> 1;
        int kbeg = (tid & 1) * 64;
        const float* Wcol = Wa + col;
#pragma unroll 8
        for (int k = kbeg; k < kbeg + 64; k++) {
            float w = __ldg(&Wcol[k * 128]);
            __nv_bfloat16 wh = __float2bfloat16(w);
            float wr = w - __bfloat162float(wh);
            __nv_bfloat16 wl = __float2bfloat16(wr);
            BH[col * KS_B + k] = *(uint16_t*)&wh;
            BL[col * KS_B + k] = *(uint16_t*)&wl;
        }
    }

    int rbase = row0 + wid * 16;
    int r0 = rbase + (lane >> 2);
    int r1 = r0 + 8;
    int r0c = (r0 < n) ? r0 : 0;
    int r1c = (r1 < n) ? r1 : 0;
    const float* A0 = A + (size_t)r0c * 128;
    const float* A1 = A + (size_t)r1c * 128;
    int cc = (lane & 3) * 2;

    uint32_t aH[8][4], aL[8][4];
#pragma unroll
    for (int ks = 0; ks < 8; ks++) {
        int k0 = ks * 16;
        float2 v00 = __ldg((const float2*)&A0[k0 + cc]);
        float2 v10 = __ldg((const float2*)&A1[k0 + cc]);
        float2 v02 = __ldg((const float2*)&A0[k0 + cc + 8]);
        float2 v12 = __ldg((const float2*)&A1[k0 + cc + 8]);
        split2(v00.x, v00.y, aH[ks][0], aL[ks][0]);
        split2(v10.x, v10.y, aH[ks][1], aL[ks][1]);
        split2(v02.x, v02.y, aH[ks][2], aL[ks][2]);
        split2(v12.x, v12.y, aH[ks][3], aL[ks][3]);
    }

    __syncthreads();

    uint32_t bh_base = smem_u32(BH);
    uint32_t bl_base = smem_u32(BL);
    uint32_t lrow = (uint32_t)(lane & 7);
    uint32_t khalf = ((uint32_t)(lane >> 3) & 1) * 8;

    bool w0 = (r0 < n), w1 = (r1 < n);
    __nv_bfloat16* C0 = C + (size_t)r0c * 128;
    __nv_bfloat16* C1 = C + (size_t)r1c * 128;

#pragma unroll 2
    for (int nb = 0; nb < 16; nb++) {
        int n0 = nb * 8;
        uint32_t off = ((n0 + lrow) * KS_B + khalf) * 2;
        uint32_t adH = bh_base + off;
        uint32_t adL = bl_base + off;
        float c0 = 0.f, c1 = 0.f, c2 = 0.f, c3 = 0.f;
#pragma unroll
        for (int ks = 0; ks < 8; ks++) {
            uint32_t bh0, bh1, bl0, bl1;
            ldsm_x2(bh0, bh1, adH + ks * 32);
            ldsm_x2(bl0, bl1, adL + ks * 32);
            mma_bf16(c0, c1, c2, c3, aH[ks][0], aH[ks][1], aH[ks][2], aH[ks][3], bh0, bh1);
            mma_bf16(c0, c1, c2, c3, aH[ks][0], aH[ks][1], aH[ks][2], aH[ks][3], bl0, bl1);
            mma_bf16(c0, c1, c2, c3, aL[ks][0], aL[ks][1], aL[ks][2], aL[ks][3], bh0, bh1);
        }
        if (w0) *(uint32_t*)&C0[n0 + cc] = bf16x2_pack(c0, c1);
        if (w1) *(uint32_t*)&C1[n0 + cc] = bf16x2_pack(c2, c3);
    }
}

// ---- gemm2: bf16 A (exact h), bf16-split B, 2-pass -------------------------
__global__ void __launch_bounds__(256)
k_mma_gemm_h(const __nv_bfloat16* __restrict__ A,
             const float* __restrict__ Wa, int Na,
             const float* __restrict__ Wb,
             __nv_bfloat16* __restrict__ C, int n) {
    extern __shared__ char smem[];
    uint16_t* BH = (uint16_t*)(smem + SOFF_BH);
    uint16_t* BL = (uint16_t*)(smem + SOFF_BL);
    int tid = threadIdx.x;
    int wid = tid >> 5, lane = tid & 31;
    int row0 = blockIdx.x * 128;
    int Nb = 128 - Na;

    {
        int col = tid >> 1;
        int kbeg = (tid & 1) * 64;
        const float* Wcol = (col < Na) ? (Wa + col) : (Wb + (col - Na));
        int stride = (col < Na) ? Na : Nb;
#pragma unroll 8
        for (int k = kbeg; k < kbeg + 64; k++) {
            float w = __ldg(&Wcol[k * stride]);
            __nv_bfloat16 wh = __float2bfloat16(w);
            float wr = w - __bfloat162float(wh);
            __nv_bfloat16 wl = __float2bfloat16(wr);
            BH[col * KS_B + k] = *(uint16_t*)&wh;
            BL[col * KS_B + k] = *(uint16_t*)&wl;
        }
    }

    int rbase = row0 + wid * 16;
    int r0 = rbase + (lane >> 2);
    int r1 = r0 + 8;
    int r0c = (r0 < n) ? r0 : 0;
    int r1c = (r1 < n) ? r1 : 0;
    const __nv_bfloat16* A0 = A + (size_t)r0c * 128;
    const __nv_bfloat16* A1 = A + (size_t)r1c * 128;
    int cc = (lane & 3) * 2;

    uint32_t a[8][4];
#pragma unroll
    for (int ks = 0; ks < 8; ks++) {
        int k0 = ks * 16;
        a[ks][0] = __ldg((const uint32_t*)&A0[k0 + cc]);
        a[ks][1] = __ldg((const uint32_t*)&A1[k0 + cc]);
        a[ks][2] = __ldg((const uint32_t*)&A0[k0 + cc + 8]);
        a[ks][3] = __ldg((const uint32_t*)&A1[k0 + cc + 8]);
    }

    __syncthreads();

    uint32_t bh_base = smem_u32(BH);
    uint32_t bl_base = smem_u32(BL);
    uint32_t lrow = (uint32_t)(lane & 7);
    uint32_t khalf = ((uint32_t)(lane >> 3) & 1) * 8;

    bool w0 = (r0 < n), w1 = (r1 < n);
    __nv_bfloat16* C0 = C + (size_t)r0c * 128;
    __nv_bfloat16* C1 = C + (size_t)r1c * 128;

#pragma unroll 2
    for (int nb = 0; nb < 16; nb++) {
        int n0 = nb * 8;
        uint32_t off = ((n0 + lrow) * KS_B + khalf) * 2;
        uint32_t adH = bh_base + off;
        uint32_t adL = bl_base + off;
        float c0 = 0.f, c1 = 0.f, c2 = 0.f, c3 = 0.f;
#pragma unroll
        for (int ks = 0; ks < 8; ks++) {
            uint32_t bh0, bh1, bl0, bl1;
            ldsm_x2(bh0, bh1, adH + ks * 32);
            ldsm_x2(bl0, bl1, adL + ks * 32);
            mma_bf16(c0, c1, c2, c3, a[ks][0], a[ks][1], a[ks][2], a[ks][3], bh0, bh1);
            mma_bf16(c0, c1, c2, c3, a[ks][0], a[ks][1], a[ks][2], a[ks][3], bl0, bl1);
        }
        if (w0) *(uint32_t*)&C0[n0 + cc] = bf16x2_pack(c0, c1);
        if (w1) *(uint32_t*)&C1[n0 + cc] = bf16x2_pack(c2, c3);
    }
}

// ---------------- launch ----------------------------------------------------
extern "C" void kernel_launch(void* const* d_in, const int* in_sizes, int n_in,
                              void* d_out, int out_size) {
    const float* x    = (const float*)d_in[0];
    const int*   ei   = (const int*)d_in[1];
    const float* initd= (const float*)d_in[2];
    const float* W1   = (const float*)d_in[3];
    const float* b1   = (const float*)d_in[4];
    const float* Wmu  = (const float*)d_in[5];
    const float* bmu  = (const float*)d_in[6];
    const float* Wls  = (const float*)d_in[7];
    const float* bls  = (const float*)d_in[8];
    float* out = (float*)d_out;

    int n = in_sizes[0] / FD;
    int e = in_sizes[1] / 2;

    void *pU = nullptr, *pH = nullptr;
    cudaGetSymbolAddress(&pU, g_bufU);
    cudaGetSymbolAddress(&pH, g_bufH);
    __nv_bfloat16* bufU = (__nv_bfloat16*)pU;
    __nv_bfloat16* bufH = (__nv_bfloat16*)pH;

    cudaFuncSetAttribute(k_mma_gemm, cudaFuncAttributeMaxDynamicSharedMemorySize, SMEM_MMA);
    cudaFuncSetAttribute(k_mma_gemm_h, cudaFuncAttributeMaxDynamicSharedMemorySize, SMEM_MMA);

    int agg_grid = (n * 32 + 255) / 256;
    int gemm_grid = (n + 127) / 128;
    int scan_grid = (n + 255) / 256;
    int fill_grid = ((e + 1) / 2 + 255) / 256;

    // layer-1 GEMM with fused degree count: U = x @ W1 (bf16)
    k_mma_gemm<<<gemm_grid, 256, SMEM_MMA>>>(x, W1, bufU, n, ei, e);

    // CSR: single-pass scan (self-cleaning), then weighted fill (+state reset)
    k_scan_lb<<<scan_grid, 256>>>(n);
    k_fill<<<fill_grid, 256>>>(ei, e);

    // h = Agg(U) + b1 (bf16)
    k_agg_bias<<<agg_grid, 256>>>(bufU, bufH, b1, n);

    // layer 2: V = h @ [Wmu|Wls] (bf16, 2-pass); out = Agg(V)+bias, reparam
    k_mma_gemm_h<<<gemm_grid, 256, SMEM_MMA>>>(bufH, Wmu, 64, Wls, bufU, n);
    k_agg_out<<<agg_grid, 256>>>(bufU, bmu, bls, initd, out, n);
}

// round 11
// speedup vs baseline: 1.4345x; 1.4345x over previous
#include <cuda_runtime.h>
#include <cuda_fp16.h>
#include <cuda_bf16.h>
#include <cstdint>
#include <math.h>

#define MAXN 100000
#define MAXE 1600000
#define FD   128      // IN == HID == 128
#define OUTC 64

// ---------------- scratch (device globals; no allocation allowed) ----------
// Invariant: g_cnt / g_status / g_ticket are zero before and after every run.
__device__ __half g_bufU[MAXN * FD];  // U (gemm1 out), later V (fp16)
__device__ float  g_bufA[MAXN * FD];  // h (agg1 out, fp32)
__device__ int    g_cnt[MAXN];
__device__ int    g_rowptr[MAXN + 1];
__device__ int    g_cursor[MAXN];
__device__ __align__(16) int2 g_csrw[MAXE];  // (src index, dinv[src] bits)
__device__ float  g_dinv[MAXN];
__device__ unsigned long long g_status[512];
__device__ unsigned int g_ticket;

// ---------------- single-pass scan (decoupled lookback) ---------------------
__global__ void k_scan_lb(int n) {
    __shared__ int s_vbid;
    __shared__ int s_excl;
    __shared__ int wsum[8], woff[8];
    int tid = threadIdx.x, lane = tid & 31, w = tid >> 5;

    if (tid == 0) s_vbid = (int)atomicAdd(&g_ticket, 1u);
    __syncthreads();
    int vbid = s_vbid;
    int i = vbid * 256 + tid;

    int val = 0;
    if (i < n) { val = g_cnt[i]; g_cnt[i] = 0; }   // consume + self-clean
    int x = val;
#pragma unroll
    for (int o = 1; o < 32; o <<= 1) {
        int t = __shfl_up_sync(0xFFFFFFFFu, x, o);
        if (lane >= o) x += t;
    }
    if (lane == 31) wsum[w] = x;
    __syncthreads();
    if (tid < 8) {
        int ws = wsum[tid];
        int y = ws;
#pragma unroll
        for (int o = 1; o < 8; o <<= 1) {
            int t = __shfl_up_sync(0xFFu, y, o);
            if (tid >= o) y += t;
        }
        woff[tid] = y - ws;
        if (tid == 7) wsum[0] = y;
    }
    __syncthreads();
    int incl = woff[w] + x;
    int agg = wsum[0];

    if (tid == 0) {
        if (vbid == 0) {
            atomicExch(&g_status[0], (2ULL << 32) | (unsigned long long)(unsigned)agg);
            s_excl = 0;
        } else {
            atomicExch(&g_status[vbid], (1ULL << 32) | (unsigned long long)(unsigned)agg);
            int sum = 0;
            int p = vbid - 1;
            while (true) {
                unsigned long long s = atomicAdd(&g_status[p], 0ULL);
                unsigned flag = (unsigned)(s >> 32);
                if (flag == 0u) continue;
                sum += (int)(unsigned)s;
                if (flag == 2u) break;
                p--;
            }
            atomicExch(&g_status[vbid], (2ULL << 32) | (unsigned long long)(unsigned)(sum + agg));
            s_excl = sum;
        }
    }
    __syncthreads();
    int base = s_excl;

    if (i < n) {
        int excl = base + incl - val;
        g_rowptr[i] = excl;
        g_cursor[i] = excl;
        g_dinv[i] = rsqrtf((float)val + 1.0f);
        if (i == n - 1) g_rowptr[n] = base + incl;
    }
}

// ---------------- CSR fill (2 edges/thread) + lookback-state cleanup --------
__global__ void k_fill(const int* __restrict__ ei, int e) {
    int gid = blockIdx.x * blockDim.x + threadIdx.x;
    if (gid < 512) g_status[gid] = 0ULL;
    if (gid == 0) g_ticket = 0u;

    int i2 = gid * 2;
    if (i2 + 1 < e) {
        int2 ss = __ldg((const int2*)&ei[i2]);
        int2 dd = __ldg((const int2*)&ei[e + i2]);
        float w0 = __ldg(&g_dinv[ss.x]);
        float w1 = __ldg(&g_dinv[ss.y]);
        int p0 = atomicAdd(&g_cursor[dd.x], 1);
        g_csrw[p0] = make_int2(ss.x, __float_as_int(w0));
        int p1 = atomicAdd(&g_cursor[dd.y], 1);
        g_csrw[p1] = make_int2(ss.y, __float_as_int(w1));
    } else if (i2 < e) {
        int s = __ldg(&ei[i2]);
        int d = __ldg(&ei[e + i2]);
        float w = __ldg(&g_dinv[s]);
        int p = atomicAdd(&g_cursor[d], 1);
        g_csrw[p] = make_int2(s, __float_as_int(w));
    }
}

// ---------------- fp16 gather core (int4 pair loads, 4-row MLP) -------------
// one warp per node; lane = 4 consecutive halves (uint2 = 8B).
__device__ __forceinline__ float4 agg_gather(const __half* __restrict__ X,
                                             int node, int lane, float di) {
    const uint2* x2 = (const uint2*)X;   // 32 uint2 per row
    uint2 sr = __ldg(&x2[(size_t)node * 32 + lane]);
    float2 f01 = __half22float2(*(__half2*)&sr.x);
    float2 f23 = __half22float2(*(__half2*)&sr.y);
    float4 acc = make_float4(di * f01.x, di * f01.y, di * f23.x, di * f23.y);

    int s0 = __ldg(&g_rowptr[node]), s1 = __ldg(&g_rowptr[node + 1]);

#define AG_FMA(rr, ww) {                                                       \
        float2 a = __half22float2(*(__half2*)&(rr).x);                         \
        float2 b = __half22float2(*(__half2*)&(rr).y);                         \
        acc.x += (ww) * a.x; acc.y += (ww) * a.y;                              \
        acc.z += (ww) * b.x; acc.w += (ww) * b.y; }

    int e = s0;
    if (e < s1 && (e & 1)) {                  // peel to even for int4 loads
        int2 p = __ldg(&g_csrw[e]);
        uint2 r = __ldg(&x2[(size_t)p.x * 32 + lane]);
        AG_FMA(r, __int_as_float(p.y));
        e++;
    }
    for (; e + 4 <= s1; e += 4) {
        int4 q0 = __ldg((const int4*)&g_csrw[e]);
        int4 q1 = __ldg((const int4*)&g_csrw[e + 2]);
        uint2 r0 = __ldg(&x2[(size_t)q0.x * 32 + lane]);
        uint2 r1 = __ldg(&x2[(size_t)q0.z * 32 + lane]);
        uint2 r2 = __ldg(&x2[(size_t)q1.x * 32 + lane]);
        uint2 r3 = __ldg(&x2[(size_t)q1.z * 32 + lane]);
        AG_FMA(r0, __int_as_float(q0.y));
        AG_FMA(r1, __int_as_float(q0.w));
        AG_FMA(r2, __int_as_float(q1.y));
        AG_FMA(r3, __int_as_float(q1.w));
    }
    if (e + 2 <= s1) {
        int4 q0 = __ldg((const int4*)&g_csrw[e]);
        uint2 r0 = __ldg(&x2[(size_t)q0.x * 32 + lane]);
        uint2 r1 = __ldg(&x2[(size_t)q0.z * 32 + lane]);
        AG_FMA(r0, __int_as_float(q0.y));
        AG_FMA(r1, __int_as_float(q0.w));
        e += 2;
    }
    if (e < s1) {
        int2 p = __ldg(&g_csrw[e]);
        uint2 r = __ldg(&x2[(size_t)p.x * 32 + lane]);
        AG_FMA(r, __int_as_float(p.y));
    }
#undef AG_FMA
    acc.x *= di; acc.y *= di; acc.z *= di; acc.w *= di;
    return acc;
}

// ---- agg1: h = Agg(U) + b1  (fp16 in, fp32 out); 128-thread blocks ---------
__global__ void __launch_bounds__(128)
k_agg_bias(const __half* __restrict__ X, float* __restrict__ Y,
           const float* __restrict__ bias, int n) {
    int gw = (blockIdx.x * blockDim.x + threadIdx.x) >> 5;
    int lane = threadIdx.x & 31;
    if (gw >= n) return;
    float di = __ldg(&g_dinv[gw]);
    float4 acc = agg_gather(X, gw, lane, di);
    float4 b = __ldg((const float4*)&bias[lane * 4]);
    acc.x += b.x; acc.y += b.y; acc.z += b.z; acc.w += b.w;
    ((float4*)Y)[(size_t)gw * 32 + lane] = acc;
}

// ---- agg2: [mu|ls] = Agg(V)+bias; out = mu + init*exp(ls) ------------------
__global__ void __launch_bounds__(128)
k_agg_out(const __half* __restrict__ X,
          const float* __restrict__ bmu, const float* __restrict__ bls,
          const float* __restrict__ initd,
          float* __restrict__ out, int n) {
    int gw = (blockIdx.x * blockDim.x + threadIdx.x) >> 5;
    int lane = threadIdx.x & 31;
    if (gw >= n) return;
    float di = __ldg(&g_dinv[gw]);
    float4 v = agg_gather(X, gw, lane, di);
    float4 b = (lane < 16) ? __ldg((const float4*)&bmu[lane * 4])
                           : __ldg((const float4*)&bls[lane * 4 - 64]);
    v.x += b.x; v.y += b.y; v.z += b.z; v.w += b.w;
    float4 p;
    p.x = __shfl_xor_sync(0xFFFFFFFFu, v.x, 16);
    p.y = __shfl_xor_sync(0xFFFFFFFFu, v.y, 16);
    p.z = __shfl_xor_sync(0xFFFFFFFFu, v.z, 16);
    p.w = __shfl_xor_sync(0xFFFFFFFFu, v.w, 16);
    if (lane < 16) {
        float4 ini = __ldg((const float4*)&initd[(size_t)gw * 64 + lane * 4]);
        float4 o;
        o.x = v.x + ini.x * expf(p.x);
        o.y = v.y + ini.y * expf(p.y);
        o.z = v.z + ini.z * expf(p.z);
        o.w = v.w + ini.w * expf(p.w);
        *(float4*)&out[(size_t)gw * 64 + lane * 4] = o;
    }
}

// ================= shared GEMM pieces =======================================
#define KS_B 136
#define SOFF_BH 0
#define SOFF_BL (128 * KS_B * 2)
#define SMEM_MMA (SOFF_BL + 128 * KS_B * 2)

__device__ __forceinline__ void split2(float a, float b, uint32_t& hi, uint32_t& lo) {
    __nv_bfloat16 ah = __float2bfloat16(a), bh = __float2bfloat16(b);
    float ar = a - __bfloat162float(ah);
    float br = b - __bfloat162float(bh);
    __nv_bfloat16 al = __float2bfloat16(ar), bl = __float2bfloat16(br);
    __nv_bfloat162 h; h.x = ah; h.y = bh;
    __nv_bfloat162 l; l.x = al; l.y = bl;
    hi = *(uint32_t*)&h;
    lo = *(uint32_t*)&l;
}

__device__ __forceinline__ uint32_t smem_u32(const void* p) {
    uint32_t a;
    asm("{ .reg .u64 t; cvta.to.shared.u64 t, %1; cvt.u32.u64 %0, t; }" : "=r"(a) : "l"(p));
    return a;
}

__device__ __forceinline__ void mma_bf16(float& c0, float& c1, float& c2, float& c3,
                                         uint32_t a0, uint32_t a1, uint32_t a2, uint32_t a3,
                                         uint32_t b0, uint32_t b1) {
    asm volatile(
        "mma.sync.aligned.m16n8k16.row.col.f32.bf16.bf16.f32 "
        "{%0,%1,%2,%3}, {%4,%5,%6,%7}, {%8,%9}, {%0,%1,%2,%3};"
        : "+f"(c0), "+f"(c1), "+f"(c2), "+f"(c3)
        : "r"(a0), "r"(a1), "r"(a2), "r"(a3), "r"(b0), "r"(b1));
}

__device__ __forceinline__ void ldsm_x2(uint32_t& r0, uint32_t& r1, uint32_t addr) {
    asm volatile("ldmatrix.sync.aligned.m8n8.x2.shared.b16 {%0, %1}, [%2];"
        : "=r"(r0), "=r"(r1) : "r"(addr));
}

// ---- generic split-bf16 3-pass GEMM: fp32 A, fp16 out ----------------------
// Na/Wb support the [Wmu|Wls] concatenation; ei!=null fuses degree count.
__global__ void __launch_bounds__(256)
k_mma_gemm(const float* __restrict__ A,
           const float* __restrict__ Wa, int Na,
           const float* __restrict__ Wb,
           __half* __restrict__ C, int n,
           const int* __restrict__ ei, int e) {
    extern __shared__ char smem[];
    uint16_t* BH = (uint16_t*)(smem + SOFF_BH);
    uint16_t* BL = (uint16_t*)(smem + SOFF_BL);
    int tid = threadIdx.x;
    int wid = tid >> 5, lane = tid & 31;
    int row0 = blockIdx.x * 128;
    int Nb = 128 - Na;

    if (ei) {
        int stride = gridDim.x * blockDim.x;
        for (int i = blockIdx.x * blockDim.x + tid; i < e; i += stride)
            atomicAdd(&g_cnt[__ldg(&ei[e + i])], 1);
    }

    {
        int col = tid >> 1;
        int kbeg = (tid & 1) * 64;
        const float* Wcol = (col < Na) ? (Wa + col) : (Wb + (col - Na));
        int stride = (col < Na) ? Na : Nb;
#pragma unroll 8
        for (int k = kbeg; k < kbeg + 64; k++) {
            float w = __ldg(&Wcol[k * stride]);
            __nv_bfloat16 wh = __float2bfloat16(w);
            float wr = w - __bfloat162float(wh);
            __nv_bfloat16 wl = __float2bfloat16(wr);
            BH[col * KS_B + k] = *(uint16_t*)&wh;
            BL[col * KS_B + k] = *(uint16_t*)&wl;
        }
    }

    int rbase = row0 + wid * 16;
    int r0 = rbase + (lane >> 2);
    int r1 = r0 + 8;
    int r0c = (r0 < n) ? r0 : 0;
    int r1c = (r1 < n) ? r1 : 0;
    const float* A0 = A + (size_t)r0c * 128;
    const float* A1 = A + (size_t)r1c * 128;
    int cc = (lane & 3) * 2;

    uint32_t aH[8][4], aL[8][4];
#pragma unroll
    for (int ks = 0; ks < 8; ks++) {
        int k0 = ks * 16;
        float2 v00 = __ldg((const float2*)&A0[k0 + cc]);
        float2 v10 = __ldg((const float2*)&A1[k0 + cc]);
        float2 v02 = __ldg((const float2*)&A0[k0 + cc + 8]);
        float2 v12 = __ldg((const float2*)&A1[k0 + cc + 8]);
        split2(v00.x, v00.y, aH[ks][0], aL[ks][0]);
        split2(v10.x, v10.y, aH[ks][1], aL[ks][1]);
        split2(v02.x, v02.y, aH[ks][2], aL[ks][2]);
        split2(v12.x, v12.y, aH[ks][3], aL[ks][3]);
    }

    __syncthreads();

    uint32_t bh_base = smem_u32(BH);
    uint32_t bl_base = smem_u32(BL);
    uint32_t lrow = (uint32_t)(lane & 7);
    uint32_t khalf = ((uint32_t)(lane >> 3) & 1) * 8;

    bool w0 = (r0 < n), w1 = (r1 < n);
    __half* C0 = C + (size_t)r0c * 128;
    __half* C1 = C + (size_t)r1c * 128;

#pragma unroll 2
    for (int nb = 0; nb < 16; nb++) {
        int n0 = nb * 8;
        uint32_t off = ((n0 + lrow) * KS_B + khalf) * 2;
        uint32_t adH = bh_base + off;
        uint32_t adL = bl_base + off;
        float c0 = 0.f, c1 = 0.f, c2 = 0.f, c3 = 0.f;
#pragma unroll
        for (int ks = 0; ks < 8; ks++) {
            uint32_t bh0, bh1, bl0, bl1;
            ldsm_x2(bh0, bh1, adH + ks * 32);
            ldsm_x2(bl0, bl1, adL + ks * 32);
            mma_bf16(c0, c1, c2, c3, aH[ks][0], aH[ks][1], aH[ks][2], aH[ks][3], bh0, bh1);
            mma_bf16(c0, c1, c2, c3, aH[ks][0], aH[ks][1], aH[ks][2], aH[ks][3], bl0, bl1);
            mma_bf16(c0, c1, c2, c3, aL[ks][0], aL[ks][1], aL[ks][2], aL[ks][3], bh0, bh1);
        }
        if (w0) *(__half2*)&C0[n0 + cc] = __floats2half2_rn(c0, c1);
        if (w1) *(__half2*)&C1[n0 + cc] = __floats2half2_rn(c2, c3);
    }
}

// ---------------- launch ----------------------------------------------------
extern "C" void kernel_launch(void* const* d_in, const int* in_sizes, int n_in,
                              void* d_out, int out_size) {
    const float* x    = (const float*)d_in[0];
    const int*   ei   = (const int*)d_in[1];
    const float* initd= (const float*)d_in[2];
    const float* W1   = (const float*)d_in[3];
    const float* b1   = (const float*)d_in[4];
    const float* Wmu  = (const float*)d_in[5];
    const float* bmu  = (const float*)d_in[6];
    const float* Wls  = (const float*)d_in[7];
    const float* bls  = (const float*)d_in[8];
    float* out = (float*)d_out;

    int n = in_sizes[0] / FD;
    int e = in_sizes[1] / 2;

    void *pU = nullptr, *pA = nullptr;
    cudaGetSymbolAddress(&pU, g_bufU);
    cudaGetSymbolAddress(&pA, g_bufA);
    __half* bufU = (__half*)pU;
    float*  bufA = (float*)pA;

    cudaFuncSetAttribute(k_mma_gemm, cudaFuncAttributeMaxDynamicSharedMemorySize, SMEM_MMA);

    int agg_grid = (n + 3) / 4;            // 128-thread blocks, 4 warps each
    int gemm_grid = (n + 127) / 128;
    int scan_grid = (n + 255) / 256;
    int fill_grid = ((e + 1) / 2 + 255) / 256;

    // layer-1 GEMM with fused degree count: U = x @ W1 (fp16)
    k_mma_gemm<<<gemm_grid, 256, SMEM_MMA>>>(x, W1, 128, W1, bufU, n, ei, e);

    // CSR: single-pass scan (self-cleaning), then weighted fill (+state reset)
    k_scan_lb<<<scan_grid, 256>>>(n);
    k_fill<<<fill_grid, 256>>>(ei, e);

    // h = Agg(U) + b1 (fp32)
    k_agg_bias<<<agg_grid, 128>>>(bufU, bufA, b1, n);

    // layer 2: V = h @ [Wmu|Wls] (fp16); out = Agg(V)+bias, reparametrized
    k_mma_gemm<<<gemm_grid, 256, SMEM_MMA>>>(bufA, Wmu, 64, Wls, bufU, n, nullptr, 0);
    k_agg_out<<<agg_grid, 128>>>(bufU, bmu, bls, initd, out, n);
}